// round 14
// baseline (speedup 1.0000x reference)
#include <cuda_runtime.h>
#include <cuda_fp16.h>
#include <math.h>

// Problem constants
#define NB   2
#define HH   256
#define WW   256
#define CC   64
#define GG   4
#define PP   9
#define NPIX (NB*HH*WW)   // 131072

typedef unsigned long long u64;

// packed f32x2 helpers
__device__ __forceinline__ u64 pk2(float v) {
    u64 r; asm("mov.b64 %0, {%1, %1};" : "=l"(r) : "f"(v)); return r;
}
__device__ __forceinline__ u64 pk(float lo, float hi) {
    u64 r; asm("mov.b64 %0, {%1, %2};" : "=l"(r) : "f"(lo), "f"(hi)); return r;
}
__device__ __forceinline__ void upk(u64 v, float& lo, float& hi) {
    asm("mov.b64 {%0, %1}, %2;" : "=f"(lo), "=f"(hi) : "l"(v));
}
__device__ __forceinline__ void fma2(u64& d, u64 a, u64 b) {
    asm("fma.rn.f32x2 %0, %1, %2, %3;" : "=l"(d) : "l"(a), "l"(b), "l"(d));
}

// cp.async helpers
__device__ __forceinline__ unsigned smem_u32(const void* p) {
    return (unsigned)__cvta_generic_to_shared(p);
}
__device__ __forceinline__ void cp16(unsigned dst, const void* src) {
    asm volatile("cp.async.cg.shared.global [%0], [%1], 16;\n"
                 :: "r"(dst), "l"(src));
}
__device__ __forceinline__ void cp16p(unsigned dst, const void* src, bool ok) {
    int sz = ok ? 16 : 0;
    asm volatile("cp.async.cg.shared.global [%0], [%1], 16, %2;\n"
                 :: "r"(dst), "l"(src), "r"(sz));
}
#define CP_COMMIT asm volatile("cp.async.commit_group;\n" ::: "memory")
#define CP_WAIT1  asm volatile("cp.async.wait_group 1;\n" ::: "memory")

// tf32 helpers
__device__ __forceinline__ unsigned tf32r(float f) {
    unsigned u; asm("cvt.rna.tf32.f32 %0, %1;" : "=r"(u) : "f"(f)); return u;
}
__device__ __forceinline__ void mma_tf32(float* c, const unsigned* a,
                                         unsigned b0, unsigned b1) {
    asm volatile(
        "mma.sync.aligned.m16n8k8.row.col.f32.tf32.tf32.f32 "
        "{%0,%1,%2,%3}, {%4,%5,%6,%7}, {%8,%9}, {%0,%1,%2,%3};"
        : "+f"(c[0]), "+f"(c[1]), "+f"(c[2]), "+f"(c[3])
        : "r"(a[0]), "r"(a[1]), "r"(a[2]), "r"(a[3]), "r"(b0), "r"(b1));
}

// Scratch (device bss — no allocation at runtime)
__device__ float  g_y[NPIX*CC];        // conv+relu output, NHWC
__device__ __half g_xproj_h[NPIX*CC];  // input projection, NHWC, fp16 storage
__device__ float  g_x1[NPIX*CC];       // dwconv+LN+GELU, NHWC
__device__ float  g_off[NPIX*72];      // raw offsets (G*P*2)
__device__ float  g_mask[NPIX*36];     // mask logits (softmax applied in k4)
__device__ float  g_wT2[8*9*512];      // conv weights tf32: [chunk][tap][oc][pair4][2]
                                       //   slot = tid4*2 + (ci>=4)  pairs (ci, ci+4)

// ---------------------------------------------------------------------------
// K0: transpose + tf32-round conv weights (oc,ci,kh,kw) -> paired layout
// ---------------------------------------------------------------------------
__global__ void k0_transpose(const float* __restrict__ w) {
    int i = blockIdx.x * blockDim.x + threadIdx.x;
    if (i < 64*64*9) {
        int oc  = i / 576;
        int ci  = (i / 9) % 64;
        int tap = i % 9;
        int chunk = ci >> 3, cil = ci & 7;
        int slot = (cil & 3) * 2 + (cil >> 2);   // pairs (ci, ci+4) adjacent
        g_wT2[((chunk*9 + tap)*64 + oc)*8 + slot] = __uint_as_float(tf32r(w[i]));
    }
}

// ---------------------------------------------------------------------------
// K1: stride-2 3x3 conv (64->64) + ReLU via tf32 mma.sync implicit GEMM.
// B-fragments now load as one LDS.64 (paired weight layout).
// ---------------------------------------------------------------------------
#define K1_PATCH 6336            // 8 * 792 floats
#define K1_WT    4608            // 9 * 64 * 8 floats
#define K1_BUF   (K1_PATCH + K1_WT)
#define K1_SMEM  (2 * K1_BUF * 4)    // bytes = 87552

__global__ __launch_bounds__(128) void k1_conv(const float* __restrict__ x) {
    extern __shared__ float sm[];

    const int w0  = blockIdx.x * 128;
    const int h   = blockIdx.y;
    const int n   = blockIdx.z;
    const int tid = threadIdx.x;
    const int warp = tid >> 5, lane = tid & 31;
    const int gid = lane >> 2, tid4 = lane & 3;
    const int pxw = warp * 32;
    const int s_col = 2*w0 - 4;

    float c[2][8][4];
    #pragma unroll
    for (int ms = 0; ms < 2; ++ms)
        #pragma unroll
        for (int ns = 0; ns < 8; ++ns)
            #pragma unroll
            for (int j = 0; j < 4; ++j) c[ms][ns][j] = 0.f;

    auto prefetch = [&](int chunk, int buf) {
        unsigned spb = smem_u32(sm + buf*K1_BUF);
        unsigned wpb = smem_u32(sm + buf*K1_BUF + K1_PATCH);
        for (int idx = tid; idx < 1584; idx += 128) {
            int ci = idx / 198;
            int r  = idx % 198;
            int ky = r / 66;
            int q  = r % 66;
            int row = 2*h - 1 + ky;
            int col = s_col + q*4;
            bool ok = ((unsigned)row < 512u) && ((unsigned)col <= 508u);
            const float* src = x + (ok ?
                ((size_t)(n*64 + chunk*8 + ci)*512 + row)*512 + col : 0);
            cp16p(spb + (unsigned)((ci*792 + ky*264 + q*4)*4), src, ok);
        }
        const float* wsrc = g_wT2 + (size_t)chunk*K1_WT;
        for (int idx = tid; idx < 1152; idx += 128)
            cp16(wpb + (unsigned)(idx*16), wsrc + idx*4);
    };

    auto compute = [&](int buf) {
        const float* pp = sm + buf*K1_BUF;
        const float* wp = pp + K1_PATCH;
        const int aB0 = tid4*792 + 2*(pxw + gid) + 3;
        const int aB1 = aB0 + 4*792;
        const int bB  = gid*8 + tid4*2;   // float2 slot
        #pragma unroll
        for (int tap = 0; tap < 9; ++tap) {
            const int ky = tap / 3, kx = tap % 3;
            const int toff = ky*264 + kx;
            unsigned a0[4], a1[4];
            a0[0] = tf32r(pp[aB0 + toff]);
            a0[1] = tf32r(pp[aB0 + toff + 16]);
            a0[2] = tf32r(pp[aB1 + toff]);
            a0[3] = tf32r(pp[aB1 + toff + 16]);
            a1[0] = tf32r(pp[aB0 + toff + 32]);
            a1[1] = tf32r(pp[aB0 + toff + 48]);
            a1[2] = tf32r(pp[aB1 + toff + 32]);
            a1[3] = tf32r(pp[aB1 + toff + 48]);
            #pragma unroll
            for (int ns = 0; ns < 8; ++ns) {
                float2 bp = *(const float2*)&wp[tap*512 + ns*64 + bB];
                unsigned b0 = __float_as_uint(bp.x);
                unsigned b1 = __float_as_uint(bp.y);
                mma_tf32(c[0][ns], a0, b0, b1);
                mma_tf32(c[1][ns], a1, b0, b1);
            }
        }
    };

    prefetch(0, 0); CP_COMMIT;
    prefetch(1, 1); CP_COMMIT;
    for (int ch = 0; ch < 8; ++ch) {
        CP_WAIT1;
        __syncthreads();
        compute(ch & 1);
        __syncthreads();
        if (ch + 2 < 8) prefetch(ch + 2, ch & 1);
        CP_COMMIT;
    }

    const int pixbase = (n*256 + h)*256 + w0 + pxw;
    #pragma unroll
    for (int ms = 0; ms < 2; ++ms) {
        #pragma unroll
        for (int rr = 0; rr < 2; ++rr) {
            int m = pixbase + ms*16 + rr*8 + gid;
            float* dst = &g_y[(size_t)m*64 + tid4*2];
            #pragma unroll
            for (int ns = 0; ns < 8; ++ns) {
                float2 v;
                v.x = fmaxf(c[ms][ns][rr*2],     0.f);
                v.y = fmaxf(c[ms][ns][rr*2 + 1], 0.f);
                *(float2*)(dst + ns*8) = v;
            }
        }
    }
}

// ---------------------------------------------------------------------------
// K2: x_proj = y @ w_in + b_in  (64x64 GEMM per 64-pixel tile), f32x2 packed,
// fp16 output for the gather stage.  (R11-validated version)
// ---------------------------------------------------------------------------
__global__ __launch_bounds__(256) void k2_xproj(const float* __restrict__ w_in,
                                                const float* __restrict__ b_in) {
    __shared__ float ys[64*65];
    __shared__ float ws[64*64];
    const int px0 = blockIdx.x * 64;
    const int tid = threadIdx.x;

    for (int idx = tid; idx < 4096; idx += 256) {
        int p = idx >> 6, k = idx & 63;
        ys[p*65 + k] = g_y[(size_t)px0*64 + idx];
        ws[idx]      = w_in[idx];
    }
    __syncthreads();

    const int ocg = tid & 15, pxg = tid >> 4;
    const int oc0 = ocg * 4, p0 = pxg * 4;
    float4 bv = *(const float4*)&b_in[oc0];
    u64 acc[4][2];
    #pragma unroll
    for (int i = 0; i < 4; ++i) { acc[i][0] = pk(bv.x, bv.y); acc[i][1] = pk(bv.z, bv.w); }

    for (int k = 0; k < 64; ++k) {
        const u64* wp = (const u64*)&ws[k*64 + oc0];
        u64 w0 = wp[0], w1 = wp[1];
        #pragma unroll
        for (int i = 0; i < 4; ++i) {
            u64 xv = pk2(ys[(p0 + i)*65 + k]);
            fma2(acc[i][0], w0, xv);
            fma2(acc[i][1], w1, xv);
        }
    }
    #pragma unroll
    for (int i = 0; i < 4; ++i) {
        float a, b, c, d;
        upk(acc[i][0], a, b); upk(acc[i][1], c, d);
        __half2 h0 = __floats2half2_rn(a, b);
        __half2 h1 = __floats2half2_rn(c, d);
        uint2 o;
        o.x = *(unsigned*)&h0; o.y = *(unsigned*)&h1;
        *(uint2*)&g_xproj_h[(size_t)(px0 + p0 + i)*64 + oc0] = o;
    }
}

// ---------------------------------------------------------------------------
// K3a: x1 = GELU(LayerNorm(dwconv3x3(y) + dw_b))    (one warp per pixel)
// ---------------------------------------------------------------------------
__global__ __launch_bounds__(256) void k3a_x1(const float* __restrict__ dw_w,
                                              const float* __restrict__ dw_b,
                                              const float* __restrict__ ln_g,
                                              const float* __restrict__ ln_b) {
    const int warp = threadIdx.x >> 5, lane = threadIdx.x & 31;
    const int px = blockIdx.x * 8 + warp;
    const int n = px >> 16, h = (px >> 8) & 255, w = px & 255;

    float v0 = dw_b[lane], v1 = dw_b[lane + 32];
    #pragma unroll
    for (int ky = 0; ky < 3; ++ky) {
        int hh = h + ky - 1;
        if (hh < 0 || hh >= 256) continue;
        #pragma unroll
        for (int kx = 0; kx < 3; ++kx) {
            int wc = w + kx - 1;
            if (wc < 0 || wc >= 256) continue;
            const float* yp = &g_y[(size_t)((n*256 + hh)*256 + wc)*64];
            int tap = ky*3 + kx;
            v0 += yp[lane]      * dw_w[tap*64 + lane];
            v1 += yp[lane + 32] * dw_w[tap*64 + lane + 32];
        }
    }
    float s  = v0 + v1;
    float sq = v0*v0 + v1*v1;
    #pragma unroll
    for (int o = 16; o > 0; o >>= 1) {
        s  += __shfl_xor_sync(0xFFFFFFFFu, s,  o);
        sq += __shfl_xor_sync(0xFFFFFFFFu, sq, o);
    }
    float m   = s * (1.f/64.f);
    float var = sq * (1.f/64.f) - m*m;
    float inv = rsqrtf(var + 1e-5f);

    {
        float t = (v0 - m)*inv*ln_g[lane] + ln_b[lane];
        g_x1[(size_t)px*64 + lane] = t * normcdff(t);
        float u = (v1 - m)*inv*ln_g[lane + 32] + ln_b[lane + 32];
        g_x1[(size_t)px*64 + lane + 32] = u * normcdff(u);
    }
}

// ---------------------------------------------------------------------------
// K3b: offset/mask 64x112 GEMM, f32x2 packed.  (R11-validated version)
// ---------------------------------------------------------------------------
__global__ __launch_bounds__(256) void k3b_offmask(const float* __restrict__ w_off,
                                                   const float* __restrict__ b_off,
                                                   const float* __restrict__ w_mask,
                                                   const float* __restrict__ b_mask) {
    __shared__ float xs[64*65];
    __shared__ float ws[64*112];
    const int px0 = blockIdx.x * 64;
    const int tid = threadIdx.x;

    for (int idx = tid; idx < 4096; idx += 256) {
        int p = idx >> 6, k = idx & 63;
        xs[p*65 + k] = g_x1[(size_t)px0*64 + idx];
    }
    for (int idx = tid; idx < 64*112; idx += 256) {
        int k = idx / 112, oc = idx % 112;
        float v = 0.f;
        if (oc < 72)       v = w_off[k*72 + oc];
        else if (oc < 108) v = w_mask[k*36 + oc - 72];
        ws[idx] = v;
    }
    __syncthreads();

    const int ocg = tid & 15, pxg = tid >> 4;
    const int p0 = pxg * 4;

    for (int half = 0; half < 2; ++half) {
        int oc0 = ocg*4 + half*64;
        if (oc0 >= 112) break;
        u64 acc[4][2];
        {
            float bb[4];
            #pragma unroll
            for (int j = 0; j < 4; ++j) {
                int oc = oc0 + j;
                bb[j] = (oc < 72) ? b_off[oc] : ((oc < 108) ? b_mask[oc - 72] : 0.f);
            }
            #pragma unroll
            for (int i = 0; i < 4; ++i) { acc[i][0] = pk(bb[0], bb[1]); acc[i][1] = pk(bb[2], bb[3]); }
        }
        for (int k = 0; k < 64; ++k) {
            const u64* wp = (const u64*)&ws[k*112 + oc0];
            u64 w0 = wp[0], w1 = wp[1];
            #pragma unroll
            for (int i = 0; i < 4; ++i) {
                u64 xv = pk2(xs[(p0 + i)*65 + k]);
                fma2(acc[i][0], w0, xv);
                fma2(acc[i][1], w1, xv);
            }
        }
        #pragma unroll
        for (int i = 0; i < 4; ++i) {
            int px = px0 + p0 + i;
            float v01[2], v23[2];
            upk(acc[i][0], v01[0], v01[1]);
            upk(acc[i][1], v23[0], v23[1]);
            #pragma unroll
            for (int j = 0; j < 4; ++j) {
                int oc = oc0 + j;
                float v = (j < 2) ? v01[j] : v23[j - 2];
                if (oc < 72)       g_off[(size_t)px*72 + oc]       = v;
                else if (oc < 108) g_mask[(size_t)px*36 + oc - 72] = v;
            }
        }
    }
}

// ---------------------------------------------------------------------------
// K4: DCNv3 bilinear gather (fp16, branchless clamped loads) + output proj.
// ---------------------------------------------------------------------------
__global__ __launch_bounds__(256) void k4_dcn(const float* __restrict__ w_out,
                                              const float* __restrict__ b_out,
                                              float* __restrict__ out) {
    __shared__ float ws[64*64];
    __shared__ float msh[32*36];
    __shared__ float osh[32*72];
    __shared__ float dsh[32*65];

    const int px0 = blockIdx.x * 32;
    const int tid = threadIdx.x;

    for (int idx = tid; idx < 4096; idx += 256) ws[idx] = w_out[idx];
    for (int idx = tid; idx < 32*36; idx += 256) msh[idx] = g_mask[(size_t)px0*36 + idx];
    for (int idx = tid; idx < 32*72; idx += 256) osh[idx] = g_off[(size_t)px0*72 + idx];
    __syncthreads();

    if (tid < 128) {
        int p = tid >> 2, g = tid & 3;
        float* mp = &msh[p*36 + g*9];
        float mx = mp[0];
        #pragma unroll
        for (int q = 1; q < 9; ++q) mx = fmaxf(mx, mp[q]);
        float ssum = 0.f;
        #pragma unroll
        for (int q = 0; q < 9; ++q) { float e = expf(mp[q] - mx); mp[q] = e; ssum += e; }
        float r = 1.f / ssum;
        #pragma unroll
        for (int q = 0; q < 9; ++q) mp[q] *= r;
    }
    __syncthreads();

    // ---- deformable gather: branchless (clamped address, zeroed weight) ----
    {
        const int pxl = tid >> 3;
        const int sub = tid & 7;
        const int g = sub >> 1, c8 = (sub & 1) * 8;
        const int px = px0 + pxl;
        const int n = px >> 16, h = (px >> 8) & 255, w = px & 255;

        float acc[8];
        #pragma unroll
        for (int j = 0; j < 8; ++j) acc[j] = 0.f;
        const float* mrow = &msh[pxl*36 + g*9];
        const float* orow = &osh[pxl*72 + g*18];
        const __half* xbase = g_xproj_h + (size_t)n*65536*64 + g*16 + c8;

        #pragma unroll
        for (int p = 0; p < 9; ++p) {
            float mwt = mrow[p];
            float ox = orow[p*2], oy = orow[p*2 + 1];
            float ix = (float)(w + p/3) + ox;      // padded-grid coords
            float iy = (float)(h + p%3) + oy;
            float x0f = floorf(ix), y0f = floorf(iy);
            float fx = ix - x0f, fy = iy - y0f;
            int x0 = (int)x0f, y0 = (int)y0f;
            float cw[4];
            cw[0] = (1.f - fy)*(1.f - fx)*mwt;
            cw[1] = (1.f - fy)*fx*mwt;
            cw[2] = fy*(1.f - fx)*mwt;
            cw[3] = fy*fx*mwt;

            #pragma unroll
            for (int corner = 0; corner < 4; ++corner) {
                int yc = y0 + (corner >> 1);
                int xc = x0 + (corner & 1);
                bool valid = ((unsigned)(xc - 1) < 256u) && ((unsigned)(yc - 1) < 256u);
                float wgt = valid ? cw[corner] : 0.f;
                int ycl = min(max(yc, 1), 256) - 1;
                int xcl = min(max(xc, 1), 256) - 1;
                const uint4 v = __ldg((const uint4*)(xbase + ((size_t)ycl*256 + xcl)*64));
                float2 f0 = __half22float2(*(const __half2*)&v.x);
                float2 f1 = __half22float2(*(const __half2*)&v.y);
                float2 f2 = __half22float2(*(const __half2*)&v.z);
                float2 f3 = __half22float2(*(const __half2*)&v.w);
                acc[0] += wgt*f0.x; acc[1] += wgt*f0.y;
                acc[2] += wgt*f1.x; acc[3] += wgt*f1.y;
                acc[4] += wgt*f2.x; acc[5] += wgt*f2.y;
                acc[6] += wgt*f3.x; acc[7] += wgt*f3.y;
            }
        }
        float* dp = &dsh[pxl*65 + g*16 + c8];
        #pragma unroll
        for (int j = 0; j < 8; ++j) dp[j] = acc[j];
    }
    __syncthreads();

    // ---- output projection (f32x2) + NCHW store ----
    {
        const int pxl = tid & 31;
        const int ocg = tid >> 5;
        const int oc0 = ocg * 8;
        float4 b1 = *(const float4*)&b_out[oc0];
        float4 b2 = *(const float4*)&b_out[oc0 + 4];
        u64 a0 = pk(b1.x, b1.y), a1 = pk(b1.z, b1.w);
        u64 a2 = pk(b2.x, b2.y), a3 = pk(b2.z, b2.w);
        for (int k = 0; k < 64; ++k) {
            u64 xv = pk2(dsh[pxl*65 + k]);
            const u64* wp = (const u64*)&ws[k*64 + oc0];
            fma2(a0, wp[0], xv);
            fma2(a1, wp[1], xv);
            fma2(a2, wp[2], xv);
            fma2(a3, wp[3], xv);
        }
        const int px = px0 + pxl;
        const int n = px >> 16, h = (px >> 8) & 255, w = px & 255;
        size_t ob = ((size_t)(n*64 + oc0)*256 + h)*256 + w;
        float r0, r1, r2, r3, r4, r5, r6, r7;
        upk(a0, r0, r1); upk(a1, r2, r3);
        upk(a2, r4, r5); upk(a3, r6, r7);
        out[ob]             = r0;
        out[ob + 1*65536]   = r1;
        out[ob + 2*65536]   = r2;
        out[ob + 3*65536]   = r3;
        out[ob + 4*65536]   = r4;
        out[ob + 5*65536]   = r5;
        out[ob + 6*65536]   = r6;
        out[ob + 7*65536]   = r7;
    }
}

// ---------------------------------------------------------------------------
extern "C" void kernel_launch(void* const* d_in, const int* in_sizes, int n_in,
                              void* d_out, int out_size) {
    const float* x      = (const float*)d_in[0];
    const float* conv_w = (const float*)d_in[1];
    const float* w_in   = (const float*)d_in[2];
    const float* b_in   = (const float*)d_in[3];
    const float* dw_w   = (const float*)d_in[4];
    const float* dw_b   = (const float*)d_in[5];
    const float* ln_g   = (const float*)d_in[6];
    const float* ln_b   = (const float*)d_in[7];
    const float* w_off  = (const float*)d_in[8];
    const float* b_off  = (const float*)d_in[9];
    const float* w_mask = (const float*)d_in[10];
    const float* b_mask = (const float*)d_in[11];
    const float* w_out  = (const float*)d_in[12];
    const float* b_out  = (const float*)d_in[13];
    float* out = (float*)d_out;

    cudaFuncSetAttribute(k1_conv, cudaFuncAttributeMaxDynamicSharedMemorySize, K1_SMEM);

    k0_transpose<<<144, 256>>>(conv_w);
    dim3 g1(2, 256, 2);
    k1_conv<<<g1, 128, K1_SMEM>>>(x);
    k2_xproj<<<2048, 256>>>(w_in, b_in);
    k3a_x1<<<16384, 256>>>(dw_w, dw_b, ln_g, ln_b);
    k3b_offmask<<<2048, 256>>>(w_off, b_off, w_mask, b_mask);
    k4_dcn<<<4096, 256>>>(w_out, b_out, out);
}

// round 15
// speedup vs baseline: 1.4048x; 1.4048x over previous
#include <cuda_runtime.h>
#include <cuda_fp16.h>
#include <math.h>

// Problem constants
#define NB   2
#define HH   256
#define WW   256
#define CC   64
#define GG   4
#define PP   9
#define NPIX (NB*HH*WW)   // 131072

typedef unsigned long long u64;

// packed f32x2 helpers
__device__ __forceinline__ u64 pk2(float v) {
    u64 r; asm("mov.b64 %0, {%1, %1};" : "=l"(r) : "f"(v)); return r;
}
__device__ __forceinline__ u64 pk(float lo, float hi) {
    u64 r; asm("mov.b64 %0, {%1, %2};" : "=l"(r) : "f"(lo), "f"(hi)); return r;
}
__device__ __forceinline__ void upk(u64 v, float& lo, float& hi) {
    asm("mov.b64 {%0, %1}, %2;" : "=f"(lo), "=f"(hi) : "l"(v));
}
__device__ __forceinline__ void fma2(u64& d, u64 a, u64 b) {
    asm("fma.rn.f32x2 %0, %1, %2, %3;" : "=l"(d) : "l"(a), "l"(b), "l"(d));
}

// cp.async helpers
__device__ __forceinline__ unsigned smem_u32(const void* p) {
    return (unsigned)__cvta_generic_to_shared(p);
}
__device__ __forceinline__ void cp16(unsigned dst, const void* src) {
    asm volatile("cp.async.cg.shared.global [%0], [%1], 16;\n"
                 :: "r"(dst), "l"(src));
}
__device__ __forceinline__ void cp16p(unsigned dst, const void* src, bool ok) {
    int sz = ok ? 16 : 0;
    asm volatile("cp.async.cg.shared.global [%0], [%1], 16, %2;\n"
                 :: "r"(dst), "l"(src), "r"(sz));
}
#define CP_COMMIT asm volatile("cp.async.commit_group;\n" ::: "memory")
#define CP_WAIT1  asm volatile("cp.async.wait_group 1;\n" ::: "memory")
#define CP_WAIT0  asm volatile("cp.async.wait_group 0;\n" ::: "memory")

// tf32 helpers
__device__ __forceinline__ unsigned tf32r(float f) {
    unsigned u; asm("cvt.rna.tf32.f32 %0, %1;" : "=r"(u) : "f"(f)); return u;
}
__device__ __forceinline__ void mma_tf32(float* c, const unsigned* a,
                                         unsigned b0, unsigned b1) {
    asm volatile(
        "mma.sync.aligned.m16n8k8.row.col.f32.tf32.tf32.f32 "
        "{%0,%1,%2,%3}, {%4,%5,%6,%7}, {%8,%9}, {%0,%1,%2,%3};"
        : "+f"(c[0]), "+f"(c[1]), "+f"(c[2]), "+f"(c[3])
        : "r"(a[0]), "r"(a[1]), "r"(a[2]), "r"(a[3]), "r"(b0), "r"(b1));
}

// Scratch (device bss — no allocation at runtime)
__device__ float  g_y[NPIX*CC];        // conv+relu output, NHWC
__device__ __half g_xproj_h[NPIX*CC];  // input projection, NHWC, fp16 storage
__device__ float  g_x1[NPIX*CC];       // dwconv+LN+GELU, NHWC
__device__ float  g_off[NPIX*72];      // raw offsets (G*P*2)
__device__ float  g_mask[NPIX*36];     // mask logits (softmax applied in k4)
__device__ float  g_wT2[8*9*512];      // conv weights tf32: paired (ci, ci+4)

// ---------------------------------------------------------------------------
// K0: transpose + tf32-round conv weights (oc,ci,kh,kw) -> paired layout
// ---------------------------------------------------------------------------
__global__ void k0_transpose(const float* __restrict__ w) {
    int i = blockIdx.x * blockDim.x + threadIdx.x;
    if (i < 64*64*9) {
        int oc  = i / 576;
        int ci  = (i / 9) % 64;
        int tap = i % 9;
        int chunk = ci >> 3, cil = ci & 7;
        int slot = (cil & 3) * 2 + (cil >> 2);   // pairs (ci, ci+4) adjacent
        g_wT2[((chunk*9 + tap)*64 + oc)*8 + slot] = __uint_as_float(tf32r(w[i]));
    }
}

// ---------------------------------------------------------------------------
// K1: stride-2 3x3 conv (64->64) + ReLU via tf32 mma.sync implicit GEMM.
// (R14 version — paired weight LDS.64)
// ---------------------------------------------------------------------------
#define K1_PATCH 6336            // 8 * 792 floats
#define K1_WT    4608            // 9 * 64 * 8 floats
#define K1_BUF   (K1_PATCH + K1_WT)
#define K1_SMEM  (2 * K1_BUF * 4)    // bytes = 87552

__global__ __launch_bounds__(128) void k1_conv(const float* __restrict__ x) {
    extern __shared__ float sm[];

    const int w0  = blockIdx.x * 128;
    const int h   = blockIdx.y;
    const int n   = blockIdx.z;
    const int tid = threadIdx.x;
    const int warp = tid >> 5, lane = tid & 31;
    const int gid = lane >> 2, tid4 = lane & 3;
    const int pxw = warp * 32;
    const int s_col = 2*w0 - 4;

    float c[2][8][4];
    #pragma unroll
    for (int ms = 0; ms < 2; ++ms)
        #pragma unroll
        for (int ns = 0; ns < 8; ++ns)
            #pragma unroll
            for (int j = 0; j < 4; ++j) c[ms][ns][j] = 0.f;

    auto prefetch = [&](int chunk, int buf) {
        unsigned spb = smem_u32(sm + buf*K1_BUF);
        unsigned wpb = smem_u32(sm + buf*K1_BUF + K1_PATCH);
        for (int idx = tid; idx < 1584; idx += 128) {
            int ci = idx / 198;
            int r  = idx % 198;
            int ky = r / 66;
            int q  = r % 66;
            int row = 2*h - 1 + ky;
            int col = s_col + q*4;
            bool ok = ((unsigned)row < 512u) && ((unsigned)col <= 508u);
            const float* src = x + (ok ?
                ((size_t)(n*64 + chunk*8 + ci)*512 + row)*512 + col : 0);
            cp16p(spb + (unsigned)((ci*792 + ky*264 + q*4)*4), src, ok);
        }
        const float* wsrc = g_wT2 + (size_t)chunk*K1_WT;
        for (int idx = tid; idx < 1152; idx += 128)
            cp16(wpb + (unsigned)(idx*16), wsrc + idx*4);
    };

    auto compute = [&](int buf) {
        const float* pp = sm + buf*K1_BUF;
        const float* wp = pp + K1_PATCH;
        const int aB0 = tid4*792 + 2*(pxw + gid) + 3;
        const int aB1 = aB0 + 4*792;
        const int bB  = gid*8 + tid4*2;   // float2 slot
        #pragma unroll
        for (int tap = 0; tap < 9; ++tap) {
            const int ky = tap / 3, kx = tap % 3;
            const int toff = ky*264 + kx;
            unsigned a0[4], a1[4];
            a0[0] = tf32r(pp[aB0 + toff]);
            a0[1] = tf32r(pp[aB0 + toff + 16]);
            a0[2] = tf32r(pp[aB1 + toff]);
            a0[3] = tf32r(pp[aB1 + toff + 16]);
            a1[0] = tf32r(pp[aB0 + toff + 32]);
            a1[1] = tf32r(pp[aB0 + toff + 48]);
            a1[2] = tf32r(pp[aB1 + toff + 32]);
            a1[3] = tf32r(pp[aB1 + toff + 48]);
            #pragma unroll
            for (int ns = 0; ns < 8; ++ns) {
                float2 bp = *(const float2*)&wp[tap*512 + ns*64 + bB];
                unsigned b0 = __float_as_uint(bp.x);
                unsigned b1 = __float_as_uint(bp.y);
                mma_tf32(c[0][ns], a0, b0, b1);
                mma_tf32(c[1][ns], a1, b0, b1);
            }
        }
    };

    prefetch(0, 0); CP_COMMIT;
    prefetch(1, 1); CP_COMMIT;
    for (int ch = 0; ch < 8; ++ch) {
        CP_WAIT1;
        __syncthreads();
        compute(ch & 1);
        __syncthreads();
        if (ch + 2 < 8) prefetch(ch + 2, ch & 1);
        CP_COMMIT;
    }

    const int pixbase = (n*256 + h)*256 + w0 + pxw;
    #pragma unroll
    for (int ms = 0; ms < 2; ++ms) {
        #pragma unroll
        for (int rr = 0; rr < 2; ++rr) {
            int m = pixbase + ms*16 + rr*8 + gid;
            float* dst = &g_y[(size_t)m*64 + tid4*2];
            #pragma unroll
            for (int ns = 0; ns < 8; ++ns) {
                float2 v;
                v.x = fmaxf(c[ms][ns][rr*2],     0.f);
                v.y = fmaxf(c[ms][ns][rr*2 + 1], 0.f);
                *(float2*)(dst + ns*8) = v;
            }
        }
    }
}

// ---------------------------------------------------------------------------
// K2: x_proj = y @ w_in + b_in  (64x64 GEMM per 64-pixel tile), f32x2 packed,
// fp16 output for the gather stage.  (R11-validated version)
// ---------------------------------------------------------------------------
__global__ __launch_bounds__(256) void k2_xproj(const float* __restrict__ w_in,
                                                const float* __restrict__ b_in) {
    __shared__ float ys[64*65];
    __shared__ float ws[64*64];
    const int px0 = blockIdx.x * 64;
    const int tid = threadIdx.x;

    for (int idx = tid; idx < 4096; idx += 256) {
        int p = idx >> 6, k = idx & 63;
        ys[p*65 + k] = g_y[(size_t)px0*64 + idx];
        ws[idx]      = w_in[idx];
    }
    __syncthreads();

    const int ocg = tid & 15, pxg = tid >> 4;
    const int oc0 = ocg * 4, p0 = pxg * 4;
    float4 bv = *(const float4*)&b_in[oc0];
    u64 acc[4][2];
    #pragma unroll
    for (int i = 0; i < 4; ++i) { acc[i][0] = pk(bv.x, bv.y); acc[i][1] = pk(bv.z, bv.w); }

    for (int k = 0; k < 64; ++k) {
        const u64* wp = (const u64*)&ws[k*64 + oc0];
        u64 w0 = wp[0], w1 = wp[1];
        #pragma unroll
        for (int i = 0; i < 4; ++i) {
            u64 xv = pk2(ys[(p0 + i)*65 + k]);
            fma2(acc[i][0], w0, xv);
            fma2(acc[i][1], w1, xv);
        }
    }
    #pragma unroll
    for (int i = 0; i < 4; ++i) {
        float a, b, c, d;
        upk(acc[i][0], a, b); upk(acc[i][1], c, d);
        __half2 h0 = __floats2half2_rn(a, b);
        __half2 h1 = __floats2half2_rn(c, d);
        uint2 o;
        o.x = *(unsigned*)&h0; o.y = *(unsigned*)&h1;
        *(uint2*)&g_xproj_h[(size_t)(px0 + p0 + i)*64 + oc0] = o;
    }
}

// ---------------------------------------------------------------------------
// K3a: x1 = GELU(LayerNorm(dwconv3x3(y) + dw_b))    (one warp per pixel)
// float2/FMA2 rewrite: thread owns channels (2*lane, 2*lane+1).
// ---------------------------------------------------------------------------
__global__ __launch_bounds__(256) void k3a_x1(const float* __restrict__ dw_w,
                                              const float* __restrict__ dw_b,
                                              const float* __restrict__ ln_g,
                                              const float* __restrict__ ln_b) {
    const int warp = threadIdx.x >> 5, lane = threadIdx.x & 31;
    const int px = blockIdx.x * 8 + warp;
    const int n = px >> 16, h = (px >> 8) & 255, w = px & 255;
    const int ch = lane * 2;

    u64 acc = *(const u64*)&dw_b[ch];
    const u64* dwp = (const u64*)dw_w;   // [tap][32 pairs]
    #pragma unroll
    for (int ky = 0; ky < 3; ++ky) {
        int hh = h + ky - 1;
        if (hh < 0 || hh >= 256) continue;
        #pragma unroll
        for (int kx = 0; kx < 3; ++kx) {
            int wc = w + kx - 1;
            if (wc < 0 || wc >= 256) continue;
            const u64 yv = *(const u64*)&g_y[(size_t)((n*256 + hh)*256 + wc)*64 + ch];
            fma2(acc, yv, dwp[(ky*3 + kx)*32 + lane]);
        }
    }
    float v0, v1;
    upk(acc, v0, v1);
    float s  = v0 + v1;
    float sq = v0*v0 + v1*v1;
    #pragma unroll
    for (int o = 16; o > 0; o >>= 1) {
        s  += __shfl_xor_sync(0xFFFFFFFFu, s,  o);
        sq += __shfl_xor_sync(0xFFFFFFFFu, sq, o);
    }
    float m   = s * (1.f/64.f);
    float var = sq * (1.f/64.f) - m*m;
    float inv = rsqrtf(var + 1e-5f);

    {
        float2 gg = *(const float2*)&ln_g[ch];
        float2 bb = *(const float2*)&ln_b[ch];
        float t = (v0 - m)*inv*gg.x + bb.x;
        float u = (v1 - m)*inv*gg.y + bb.y;
        float2 o;
        o.x = t * normcdff(t);
        o.y = u * normcdff(u);
        *(float2*)&g_x1[(size_t)px*64 + ch] = o;
    }
}

// ---------------------------------------------------------------------------
// K3b: offset/mask 64x112 GEMM, f32x2 packed.  (R11-validated version)
// ---------------------------------------------------------------------------
__global__ __launch_bounds__(256) void k3b_offmask(const float* __restrict__ w_off,
                                                   const float* __restrict__ b_off,
                                                   const float* __restrict__ w_mask,
                                                   const float* __restrict__ b_mask) {
    __shared__ float xs[64*65];
    __shared__ float ws[64*112];
    const int px0 = blockIdx.x * 64;
    const int tid = threadIdx.x;

    for (int idx = tid; idx < 4096; idx += 256) {
        int p = idx >> 6, k = idx & 63;
        xs[p*65 + k] = g_x1[(size_t)px0*64 + idx];
    }
    for (int idx = tid; idx < 64*112; idx += 256) {
        int k = idx / 112, oc = idx % 112;
        float v = 0.f;
        if (oc < 72)       v = w_off[k*72 + oc];
        else if (oc < 108) v = w_mask[k*36 + oc - 72];
        ws[idx] = v;
    }
    __syncthreads();

    const int ocg = tid & 15, pxg = tid >> 4;
    const int p0 = pxg * 4;

    for (int half = 0; half < 2; ++half) {
        int oc0 = ocg*4 + half*64;
        if (oc0 >= 112) break;
        u64 acc[4][2];
        {
            float bb[4];
            #pragma unroll
            for (int j = 0; j < 4; ++j) {
                int oc = oc0 + j;
                bb[j] = (oc < 72) ? b_off[oc] : ((oc < 108) ? b_mask[oc - 72] : 0.f);
            }
            #pragma unroll
            for (int i = 0; i < 4; ++i) { acc[i][0] = pk(bb[0], bb[1]); acc[i][1] = pk(bb[2], bb[3]); }
        }
        for (int k = 0; k < 64; ++k) {
            const u64* wp = (const u64*)&ws[k*112 + oc0];
            u64 w0 = wp[0], w1 = wp[1];
            #pragma unroll
            for (int i = 0; i < 4; ++i) {
                u64 xv = pk2(xs[(p0 + i)*65 + k]);
                fma2(acc[i][0], w0, xv);
                fma2(acc[i][1], w1, xv);
            }
        }
        #pragma unroll
        for (int i = 0; i < 4; ++i) {
            int px = px0 + p0 + i;
            float v01[2], v23[2];
            upk(acc[i][0], v01[0], v01[1]);
            upk(acc[i][1], v23[0], v23[1]);
            #pragma unroll
            for (int j = 0; j < 4; ++j) {
                int oc = oc0 + j;
                float v = (j < 2) ? v01[j] : v23[j - 2];
                if (oc < 72)       g_off[(size_t)px*72 + oc]       = v;
                else if (oc < 108) g_mask[(size_t)px*36 + oc - 72] = v;
            }
        }
    }
}

// ---------------------------------------------------------------------------
// K4: DCNv3 bilinear gather from a 6x38 smem tile (global fallback for
// out-of-window samples) + softmax + output projection -> NCHW output.
// 32 px/block, 256 threads.
// smem layout (dynamic): tile fp16 | ws | msh | osh | dsh
// ---------------------------------------------------------------------------
#define K4_TILE_B  29184                         // 6*38*64 halves
#define K4_WS_B    16384
#define K4_MSH_B   4608
#define K4_OSH_B   9216
#define K4_DSH_B   8320
#define K4_SMEM    (K4_TILE_B + K4_WS_B + K4_MSH_B + K4_OSH_B + K4_DSH_B)  // 67712

__global__ __launch_bounds__(256) void k4_dcn(const float* __restrict__ w_out,
                                              const float* __restrict__ b_out,
                                              float* __restrict__ out) {
    extern __shared__ char sm4[];
    __half* tile = (__half*)sm4;
    float*  ws   = (float*)(sm4 + K4_TILE_B);
    float*  msh  = (float*)(sm4 + K4_TILE_B + K4_WS_B);
    float*  osh  = (float*)(sm4 + K4_TILE_B + K4_WS_B + K4_MSH_B);
    float*  dsh  = (float*)(sm4 + K4_TILE_B + K4_WS_B + K4_MSH_B + K4_OSH_B);

    const int px0 = blockIdx.x * 32;
    const int tid = threadIdx.x;
    const int n  = px0 >> 16, h = (px0 >> 8) & 255, w0 = px0 & 255;

    // tile fill: rows h-2..h+3, cols w0-2..w0+35, zfill outside image
    {
        unsigned tb = smem_u32(tile);
        for (int idx = tid; idx < 1824; idx += 256) {
            int r   = idx / 304;          // 38 cols * 8 chunks
            int rem = idx % 304;
            int cx  = rem >> 3;
            int c16 = rem & 7;
            int row = h - 2 + r, col = w0 - 2 + cx;
            bool ok = ((unsigned)row < 256u) && ((unsigned)col < 256u);
            const __half* src = g_xproj_h +
                (ok ? (((size_t)(n*256 + row)*256 + col)*64 + c16*8) : 0);
            cp16p(tb + (unsigned)idx*16, src, ok);
        }
    }
    for (int idx = tid; idx < 4096; idx += 256) ws[idx] = w_out[idx];
    for (int idx = tid; idx < 32*36; idx += 256) msh[idx] = g_mask[(size_t)px0*36 + idx];
    for (int idx = tid; idx < 32*72; idx += 256) osh[idx] = g_off[(size_t)px0*72 + idx];
    CP_COMMIT; CP_WAIT0;
    __syncthreads();

    // softmax over P per (pixel, group)
    if (tid < 128) {
        int p = tid >> 2, g = tid & 3;
        float* mp = &msh[p*36 + g*9];
        float mx = mp[0];
        #pragma unroll
        for (int q = 1; q < 9; ++q) mx = fmaxf(mx, mp[q]);
        float ssum = 0.f;
        #pragma unroll
        for (int q = 0; q < 9; ++q) { float e = expf(mp[q] - mx); mp[q] = e; ssum += e; }
        float r = 1.f / ssum;
        #pragma unroll
        for (int q = 0; q < 9; ++q) mp[q] *= r;
    }
    __syncthreads();

    // ---- deformable gather (smem tile + rare global fallback) ----
    {
        const int pxl = tid >> 3;
        const int sub = tid & 7;
        const int g = sub >> 1, c8 = (sub & 1) * 8;
        const int px = px0 + pxl;
        const int w = px & 255;
        const int hoff = g*16 + c8;

        float acc[8];
        #pragma unroll
        for (int j = 0; j < 8; ++j) acc[j] = 0.f;
        const float* mrow = &msh[pxl*36 + g*9];
        const float* orow = &osh[pxl*72 + g*18];

        #pragma unroll
        for (int p = 0; p < 9; ++p) {
            float mwt = mrow[p];
            float ox = orow[p*2], oy = orow[p*2 + 1];
            float ix = (float)(w + p/3) + ox;      // padded-grid coords
            float iy = (float)(h + p%3) + oy;
            float x0f = floorf(ix), y0f = floorf(iy);
            float fx = ix - x0f, fy = iy - y0f;
            int x0 = (int)x0f, y0 = (int)y0f;
            float cw[4];
            cw[0] = (1.f - fy)*(1.f - fx)*mwt;
            cw[1] = (1.f - fy)*fx*mwt;
            cw[2] = fy*(1.f - fx)*mwt;
            cw[3] = fy*fx*mwt;

            #pragma unroll
            for (int corner = 0; corner < 4; ++corner) {
                int yc = y0 + (corner >> 1);
                int xc = x0 + (corner & 1);
                bool valid = ((unsigned)(xc - 1) < 256u) && ((unsigned)(yc - 1) < 256u);
                float wgt = valid ? cw[corner] : 0.f;
                int tr = yc - h + 1;     // (yc-1) - (h-2)
                int tc = xc - w0 + 1;    // (xc-1) - (w0-2)
                uint4 v;
                if ((unsigned)tr < 6u && (unsigned)tc < 38u) {
                    v = *(const uint4*)(tile + ((tr*38 + tc)*64 + hoff));
                } else {
                    int ycl = min(max(yc, 1), 256) - 1;
                    int xcl = min(max(xc, 1), 256) - 1;
                    v = *(const uint4*)(g_xproj_h +
                        (((size_t)(n*256 + ycl)*256 + xcl)*64 + hoff));
                }
                float2 f0 = __half22float2(*(const __half2*)&v.x);
                float2 f1 = __half22float2(*(const __half2*)&v.y);
                float2 f2 = __half22float2(*(const __half2*)&v.z);
                float2 f3 = __half22float2(*(const __half2*)&v.w);
                acc[0] += wgt*f0.x; acc[1] += wgt*f0.y;
                acc[2] += wgt*f1.x; acc[3] += wgt*f1.y;
                acc[4] += wgt*f2.x; acc[5] += wgt*f2.y;
                acc[6] += wgt*f3.x; acc[7] += wgt*f3.y;
            }
        }
        float* dp = &dsh[pxl*65 + g*16 + c8];
        #pragma unroll
        for (int j = 0; j < 8; ++j) dp[j] = acc[j];
    }
    __syncthreads();

    // ---- output projection (f32x2) + NCHW store ----
    {
        const int pxl = tid & 31;
        const int ocg = tid >> 5;
        const int oc0 = ocg * 8;
        float4 b1 = *(const float4*)&b_out[oc0];
        float4 b2 = *(const float4*)&b_out[oc0 + 4];
        u64 a0 = pk(b1.x, b1.y), a1 = pk(b1.z, b1.w);
        u64 a2 = pk(b2.x, b2.y), a3 = pk(b2.z, b2.w);
        for (int k = 0; k < 64; ++k) {
            u64 xv = pk2(dsh[pxl*65 + k]);
            const u64* wp = (const u64*)&ws[k*64 + oc0];
            fma2(a0, wp[0], xv);
            fma2(a1, wp[1], xv);
            fma2(a2, wp[2], xv);
            fma2(a3, wp[3], xv);
        }
        const int px = px0 + pxl;
        const int nn = px >> 16, hh2 = (px >> 8) & 255, ww2 = px & 255;
        size_t ob = ((size_t)(nn*64 + oc0)*256 + hh2)*256 + ww2;
        float r0, r1, r2, r3, r4, r5, r6, r7;
        upk(a0, r0, r1); upk(a1, r2, r3);
        upk(a2, r4, r5); upk(a3, r6, r7);
        out[ob]             = r0;
        out[ob + 1*65536]   = r1;
        out[ob + 2*65536]   = r2;
        out[ob + 3*65536]   = r3;
        out[ob + 4*65536]   = r4;
        out[ob + 5*65536]   = r5;
        out[ob + 6*65536]   = r6;
        out[ob + 7*65536]   = r7;
    }
}

// ---------------------------------------------------------------------------
extern "C" void kernel_launch(void* const* d_in, const int* in_sizes, int n_in,
                              void* d_out, int out_size) {
    const float* x      = (const float*)d_in[0];
    const float* conv_w = (const float*)d_in[1];
    const float* w_in   = (const float*)d_in[2];
    const float* b_in   = (const float*)d_in[3];
    const float* dw_w   = (const float*)d_in[4];
    const float* dw_b   = (const float*)d_in[5];
    const float* ln_g   = (const float*)d_in[6];
    const float* ln_b   = (const float*)d_in[7];
    const float* w_off  = (const float*)d_in[8];
    const float* b_off  = (const float*)d_in[9];
    const float* w_mask = (const float*)d_in[10];
    const float* b_mask = (const float*)d_in[11];
    const float* w_out  = (const float*)d_in[12];
    const float* b_out  = (const float*)d_in[13];
    float* out = (float*)d_out;

    cudaFuncSetAttribute(k1_conv, cudaFuncAttributeMaxDynamicSharedMemorySize, K1_SMEM);
    cudaFuncSetAttribute(k4_dcn,  cudaFuncAttributeMaxDynamicSharedMemorySize, K4_SMEM);

    k0_transpose<<<144, 256>>>(conv_w);
    dim3 g1(2, 256, 2);
    k1_conv<<<g1, 128, K1_SMEM>>>(x);
    k2_xproj<<<2048, 256>>>(w_in, b_in);
    k3a_x1<<<16384, 256>>>(dw_w, dw_b, ln_g, ln_b);
    k3b_offmask<<<2048, 256>>>(w_off, b_off, w_mask, b_mask);
    k4_dcn<<<4096, 256, K4_SMEM>>>(w_out, b_out, out);
}